// round 3
// baseline (speedup 1.0000x reference)
#include <cuda_runtime.h>
#include <cuda_bf16.h>

// Problem constants (from reference setup_inputs)
#define IN_G    64
#define OUT_G   64
#define IN_MEM  8
#define OUT_MEM 8
#define N_EMBED 512
#define DIMQ    64          // IN_MEM*OUT_MEM
#define NROWS   4096        // IN_G*OUT_G
#define KDIM    512         // IN_G*IN_MEM
#define NDIM    512         // OUT_G*OUT_MEM

// Scratch (no cudaMalloc allowed)
__device__ float  d_Wq[KDIM * NDIM];     // quantized weight in GEMM layout [512,512]
__device__ float  d_e2[N_EMBED];         // ||e_j||^2
__device__ double d_diff_acc;            // sum of squared diffs

// ---------------------------------------------------------------------------
// init: per-code squared norms + zero accumulator
// ---------------------------------------------------------------------------
__global__ void init_kernel(const float* __restrict__ embed) {
    int j = threadIdx.x;            // 0..511
    float s = 0.f;
    #pragma unroll 8
    for (int d = 0; d < DIMQ; ++d) {
        float e = embed[d * N_EMBED + j];
        s += e * e;
    }
    d_e2[j] = s;
    if (j == 0) d_diff_acc = 0.0;
}

// ---------------------------------------------------------------------------
// quantize: 128 blocks x 256 threads. 8 threads per weight row; thread `sub`
// scans codes [sub*64, sub*64+64). Butterfly argmin with first-index
// tie-break (matches jnp.argmin). Winner's code row is scattered into the
// permuted GEMM layout; squared diff accumulated into d_diff_acc.
// ---------------------------------------------------------------------------
__global__ __launch_bounds__(256) void quantize_kernel(
    const float* __restrict__ w,        // [4096,64] flat
    const float* __restrict__ embed)    // [64,512]
{
    const int t   = threadIdx.x;
    const int sub = t & 7;              // 0..7 (code partition)
    const int rl  = t >> 3;             // 0..31 (row within block)
    const int row = blockIdx.x * 32 + rl;
    const float* wrow = w + row * DIMQ;
    const int jbase = sub * 64;

    float dots[64];
    #pragma unroll
    for (int c = 0; c < 64; ++c) dots[c] = 0.f;

    // dot of w row against 64 codes; embed row d is read as float4s
    #pragma unroll 2
    for (int d = 0; d < DIMQ; ++d) {
        float wd = __ldg(wrow + d);
        const float4* er = (const float4*)(embed + d * N_EMBED + jbase);
        #pragma unroll
        for (int c4 = 0; c4 < 16; ++c4) {
            float4 e = __ldg(er + c4);
            dots[c4 * 4 + 0] += wd * e.x;
            dots[c4 * 4 + 1] += wd * e.y;
            dots[c4 * 4 + 2] += wd * e.z;
            dots[c4 * 4 + 3] += wd * e.w;
        }
    }

    // score = ||e||^2 - 2 w.e  (||w||^2 is row-constant -> irrelevant to argmin)
    float best = 3.4e38f;
    int   bidx = jbase;
    #pragma unroll
    for (int c = 0; c < 64; ++c) {
        float s = d_e2[jbase + c] - 2.f * dots[c];
        if (s < best) { best = s; bidx = jbase + c; }   // strict < keeps lowest c
    }

    // butterfly argmin across the 8 lanes of this row; prefer smaller index on tie
    #pragma unroll
    for (int off = 4; off >= 1; off >>= 1) {
        float ob = __shfl_xor_sync(0xffffffffu, best, off);
        int   oi = __shfl_xor_sync(0xffffffffu, bidx, off);
        if (ob < best || (ob == best && oi < bidx)) { best = ob; bidx = oi; }
    }
    // all 8 lanes now agree on bidx

    // scatter quant into GEMM layout + local squared diff
    // w_flat row = ig*64+og ; element d = i*8+om ; with d = sub*8+k: i=sub, om=k
    const int ig = row >> 6;
    const int og = row & 63;
    float qv[8];
    float local = 0.f;
    #pragma unroll
    for (int k = 0; k < 8; ++k) {
        int d = sub * 8 + k;
        float q  = __ldg(embed + d * N_EMBED + bidx);
        float wv = __ldg(wrow + d);
        float df = q - wv;
        local += df * df;
        qv[k] = q;
    }
    float4* dst = (float4*)(d_Wq + (ig * 8 + sub) * NDIM + og * 8);
    dst[0] = make_float4(qv[0], qv[1], qv[2], qv[3]);
    dst[1] = make_float4(qv[4], qv[5], qv[6], qv[7]);

    // warp-reduce diff, one double atomic per warp
    #pragma unroll
    for (int off = 16; off >= 1; off >>= 1)
        local += __shfl_xor_sync(0xffffffffu, local, off);
    if ((t & 31) == 0) atomicAdd(&d_diff_acc, (double)local);
}

// ---------------------------------------------------------------------------
// SGEMM: C[b,o] = A[8192,512] @ d_Wq[512,512], fp32.
// 128x128 block tile, BK=8, double-buffered smem, 256 threads, 8x8 microtile.
// ---------------------------------------------------------------------------
__global__ __launch_bounds__(256) void gemm_kernel(
    const float* __restrict__ A,    // x [B,512]
    float* __restrict__ C)          // res [B,512]
{
    __shared__ float As[2][8][128];   // [k][m]
    __shared__ float Bs[2][8][128];   // [k][n]

    const int tid = threadIdx.x;
    const int m0 = blockIdx.y * 128;
    const int n0 = blockIdx.x * 128;

    const int a_m = tid >> 1;            // 0..127
    const int a_k = (tid & 1) * 4;       // 0 or 4
    const int b_k = tid >> 5;            // 0..7
    const int b_n = (tid & 31) * 4;      // 0..124

    const int tx = tid & 15;             // n micro
    const int ty = tid >> 4;             // m micro

    // prologue: tile 0
    {
        float4 av = *(const float4*)(A + (long)(m0 + a_m) * KDIM + a_k);
        As[0][a_k + 0][a_m] = av.x;
        As[0][a_k + 1][a_m] = av.y;
        As[0][a_k + 2][a_m] = av.z;
        As[0][a_k + 3][a_m] = av.w;
        *(float4*)&Bs[0][b_k][b_n] = *(const float4*)(d_Wq + b_k * NDIM + n0 + b_n);
    }
    __syncthreads();

    float acc[8][8];
    #pragma unroll
    for (int i = 0; i < 8; ++i)
        #pragma unroll
        for (int j = 0; j < 8; ++j) acc[i][j] = 0.f;

    int buf = 0;
    for (int kt = 0; kt < KDIM; kt += 8) {
        const int nxt = buf ^ 1;
        if (kt + 8 < KDIM) {
            float4 av = *(const float4*)(A + (long)(m0 + a_m) * KDIM + kt + 8 + a_k);
            As[nxt][a_k + 0][a_m] = av.x;
            As[nxt][a_k + 1][a_m] = av.y;
            As[nxt][a_k + 2][a_m] = av.z;
            As[nxt][a_k + 3][a_m] = av.w;
            *(float4*)&Bs[nxt][b_k][b_n] =
                *(const float4*)(d_Wq + (kt + 8 + b_k) * NDIM + n0 + b_n);
        }
        #pragma unroll
        for (int k = 0; k < 8; ++k) {
            float a[8], b[8];
            *(float4*)&a[0] = *(const float4*)&As[buf][k][ty * 8];
            *(float4*)&a[4] = *(const float4*)&As[buf][k][ty * 8 + 4];
            *(float4*)&b[0] = *(const float4*)&Bs[buf][k][tx * 8];
            *(float4*)&b[4] = *(const float4*)&Bs[buf][k][tx * 8 + 4];
            #pragma unroll
            for (int i = 0; i < 8; ++i)
                #pragma unroll
                for (int j = 0; j < 8; ++j)
                    acc[i][j] += a[i] * b[j];
        }
        __syncthreads();
        buf = nxt;
    }

    #pragma unroll
    for (int i = 0; i < 8; ++i) {
        float* cp = C + (long)(m0 + ty * 8 + i) * NDIM + n0 + tx * 8;
        *(float4*)(cp)     = make_float4(acc[i][0], acc[i][1], acc[i][2], acc[i][3]);
        *(float4*)(cp + 4) = make_float4(acc[i][4], acc[i][5], acc[i][6], acc[i][7]);
    }
}

// ---------------------------------------------------------------------------
// finalize: diff = mean of squared diffs, appended after res
// ---------------------------------------------------------------------------
__global__ void finalize_kernel(float* __restrict__ out, long n_res, long out_size) {
    if (out_size > n_res)
        out[n_res] = (float)(d_diff_acc * (1.0 / (double)(NROWS * DIMQ)));
}

// ---------------------------------------------------------------------------
// launch
// ---------------------------------------------------------------------------
extern "C" void kernel_launch(void* const* d_in, const int* in_sizes, int n_in,
                              void* d_out, int out_size) {
    const float* x      = (const float*)d_in[0];   // [B, 512]
    const float* weight = (const float*)d_in[1];   // [4096, 64] flat
    const float* embed  = (const float*)d_in[2];   // [64, 512]
    float* out = (float*)d_out;

    const int b = in_sizes[0] / KDIM;              // 8192

    init_kernel<<<1, N_EMBED>>>(embed);
    quantize_kernel<<<NROWS / 32, 256>>>(weight, embed);

    dim3 grid(NDIM / 128, b / 128);                // (4, 64)
    gemm_kernel<<<grid, 256>>>(x, out);

    finalize_kernel<<<1, 1>>>(out, (long)b * NDIM, (long)out_size);
}

// round 6
// speedup vs baseline: 1.2570x; 1.2570x over previous
#include <cuda_runtime.h>
#include <cuda_bf16.h>
#include <cstdint>

// Problem constants
#define N_EMBED 512
#define DIMQ    64          // IN_MEM*OUT_MEM
#define NROWS   4096        // IN_G*OUT_G
#define KDIM    512
#define NDIM    512

// Scratch (no cudaMalloc allowed)
__device__ float          d_Wq[KDIM * NDIM];      // quantized weight fp32 [k][n]
__device__ __nv_bfloat16  d_WtHi[NDIM * KDIM];    // W^T hi  [n][k]
__device__ __nv_bfloat16  d_WtLo[NDIM * KDIM];    // W^T lo  [n][k]
__device__ float          d_e2[N_EMBED];
__device__ double         d_diff_acc;

// ---------------------------------------------------------------------------
// helpers
// ---------------------------------------------------------------------------
__device__ __forceinline__ uint32_t smem_u32(const void* p) {
    uint32_t a;
    asm("{ .reg .u64 t; cvta.to.shared.u64 t, %1; cvt.u32.u64 %0, t; }" : "=r"(a) : "l"(p));
    return a;
}
__device__ __forceinline__ void split2(float a, float b, uint32_t& h, uint32_t& l) {
    __nv_bfloat16 ah = __float2bfloat16_rn(a);
    __nv_bfloat16 bh = __float2bfloat16_rn(b);
    __nv_bfloat16 al = __float2bfloat16_rn(a - __bfloat162float(ah));
    __nv_bfloat16 bl = __float2bfloat16_rn(b - __bfloat162float(bh));
    __nv_bfloat162 hv; hv.x = ah; hv.y = bh;
    __nv_bfloat162 lv; lv.x = al; lv.y = bl;
    h = *(uint32_t*)&hv; l = *(uint32_t*)&lv;
}
__device__ __forceinline__ void ldsm4(uint32_t* r, uint32_t addr) {
    asm volatile("ldmatrix.sync.aligned.m8n8.x4.shared.b16 {%0,%1,%2,%3}, [%4];"
                 : "=r"(r[0]), "=r"(r[1]), "=r"(r[2]), "=r"(r[3]) : "r"(addr));
}
__device__ __forceinline__ void mma16816(float* c, const uint32_t* a,
                                         uint32_t b0, uint32_t b1) {
    asm volatile("mma.sync.aligned.m16n8k16.row.col.f32.bf16.bf16.f32 "
                 "{%0,%1,%2,%3}, {%4,%5,%6,%7}, {%8,%9}, {%0,%1,%2,%3};"
                 : "+f"(c[0]), "+f"(c[1]), "+f"(c[2]), "+f"(c[3])
                 : "r"(a[0]), "r"(a[1]), "r"(a[2]), "r"(a[3]), "r"(b0), "r"(b1));
}

// ---------------------------------------------------------------------------
// init: per-code squared norms + zero accumulator
// ---------------------------------------------------------------------------
__global__ void init_kernel(const float* __restrict__ embed) {
    int j = threadIdx.x;
    float s = 0.f;
    #pragma unroll 8
    for (int d = 0; d < DIMQ; ++d) {
        float e = embed[d * N_EMBED + j];
        s += e * e;
    }
    d_e2[j] = s;
    if (j == 0) d_diff_acc = 0.0;
}

// ---------------------------------------------------------------------------
// quantize (R3 passing version, unchanged)
// ---------------------------------------------------------------------------
__global__ __launch_bounds__(256) void quantize_kernel(
    const float* __restrict__ w,
    const float* __restrict__ embed)
{
    const int t   = threadIdx.x;
    const int sub = t & 7;
    const int rl  = t >> 3;
    const int row = blockIdx.x * 32 + rl;
    const float* wrow = w + row * DIMQ;
    const int jbase = sub * 64;

    float dots[64];
    #pragma unroll
    for (int c = 0; c < 64; ++c) dots[c] = 0.f;

    #pragma unroll 2
    for (int d = 0; d < DIMQ; ++d) {
        float wd = __ldg(wrow + d);
        const float4* er = (const float4*)(embed + d * N_EMBED + jbase);
        #pragma unroll
        for (int c4 = 0; c4 < 16; ++c4) {
            float4 e = __ldg(er + c4);
            dots[c4 * 4 + 0] += wd * e.x;
            dots[c4 * 4 + 1] += wd * e.y;
            dots[c4 * 4 + 2] += wd * e.z;
            dots[c4 * 4 + 3] += wd * e.w;
        }
    }

    float best = 3.4e38f;
    int   bidx = jbase;
    #pragma unroll
    for (int c = 0; c < 64; ++c) {
        float s = d_e2[jbase + c] - 2.f * dots[c];
        if (s < best) { best = s; bidx = jbase + c; }
    }

    #pragma unroll
    for (int off = 4; off >= 1; off >>= 1) {
        float ob = __shfl_xor_sync(0xffffffffu, best, off);
        int   oi = __shfl_xor_sync(0xffffffffu, bidx, off);
        if (ob < best || (ob == best && oi < bidx)) { best = ob; bidx = oi; }
    }

    const int ig = row >> 6;
    const int og = row & 63;
    float qv[8];
    float local = 0.f;
    #pragma unroll
    for (int k = 0; k < 8; ++k) {
        int d = sub * 8 + k;
        float q  = __ldg(embed + d * N_EMBED + bidx);
        float wv = __ldg(wrow + d);
        float df = q - wv;
        local += df * df;
        qv[k] = q;
    }
    float4* dst = (float4*)(d_Wq + (ig * 8 + sub) * NDIM + og * 8);
    dst[0] = make_float4(qv[0], qv[1], qv[2], qv[3]);
    dst[1] = make_float4(qv[4], qv[5], qv[6], qv[7]);

    #pragma unroll
    for (int off = 16; off >= 1; off >>= 1)
        local += __shfl_xor_sync(0xffffffffu, local, off);
    if ((t & 31) == 0) atomicAdd(&d_diff_acc, (double)local);
}

// ---------------------------------------------------------------------------
// split: transpose d_Wq [k][n] -> Wt[n][k] as bf16 hi/lo pair
// ---------------------------------------------------------------------------
__global__ void split_kernel() {
    __shared__ float tile[32][33];
    const int tx = threadIdx.x, ty = threadIdx.y;
    const int bx = blockIdx.x, by = blockIdx.y;
    #pragma unroll
    for (int i = 0; i < 4; ++i)
        tile[ty + i * 8][tx] = d_Wq[(by * 32 + ty + i * 8) * NDIM + bx * 32 + tx];
    __syncthreads();
    #pragma unroll
    for (int i = 0; i < 4; ++i) {
        float v = tile[tx][ty + i * 8];
        __nv_bfloat16 h = __float2bfloat16_rn(v);
        __nv_bfloat16 l = __float2bfloat16_rn(v - __bfloat162float(h));
        int n = bx * 32 + ty + i * 8;
        int k = by * 32 + tx;
        d_WtHi[n * KDIM + k] = h;
        d_WtLo[n * KDIM + k] = l;
    }
}

// ---------------------------------------------------------------------------
// HMMA GEMM: C[8192,512] = x @ W via bf16 split (3 products), fp32 accum.
// CTA 128x128, 8 warps (warp tile 32x64), BK=32 fp32 per chunk, 16 chunks,
// double-buffered smem (hi/lo A + hi/lo Wt), cp.async for W, mma.sync bf16.
// ---------------------------------------------------------------------------
#define BK      32
#define NCH     (KDIM / BK)         // 16
#define RS      80                  // smem row stride bytes (32 bf16 + pad), 16B-multiple
#define MATB    (128 * RS)          // 10240 per matrix
#define STAGEB  (4 * MATB)          // 40960 per stage (Ahi, Alo, Whi, Wlo)
#define SMEMB   (2 * STAGEB)        // 81920

__global__ __launch_bounds__(256) void gemm_mma_kernel(
    const float* __restrict__ A,    // x [B,512]
    float* __restrict__ C)          // res [B,512]
{
    extern __shared__ char smem[];
    const uint32_t sb = smem_u32(smem);
    const int tid  = threadIdx.x;
    const int lane = tid & 31;
    const int wid  = tid >> 5;
    const int m0 = blockIdx.y * 128;
    const int n0 = blockIdx.x * 128;
    const int wm = (wid & 3) * 32;      // warp M origin in tile
    const int wn = (wid >> 2) * 64;     // warp N origin in tile

    // ldmatrix lane offsets (bytes within a matrix region)
    const uint32_t aOff = (uint32_t)(wm + (lane & 15)) * RS + ((lane >> 4) * 16);
    const uint32_t bOff = (uint32_t)(wn + ((lane >> 4) * 8) + (lane & 7)) * RS
                        + (((lane >> 3) & 1) * 16);

    // A global staging: thread covers row (tid>>1), 16 cols at (tid&1)*16
    const int ar = tid >> 1;
    const int ac = (tid & 1) * 16;
    const float* aG = A + (size_t)(m0 + ar) * KDIM + ac;
    const uint32_t aStoreOff = (uint32_t)ar * RS + (uint32_t)ac * 2;

    // W cp.async: tid<128 -> hi row tid; tid>=128 -> lo row tid-128 (64B each)
    const int wrow = tid & 127;
    const __nv_bfloat16* wG = ((tid < 128) ? d_WtHi : d_WtLo) + (size_t)(n0 + wrow) * KDIM;
    const uint32_t wStoreOff = ((tid < 128) ? 0u : (uint32_t)MATB) + (uint32_t)wrow * RS;

    float acc[2][8][4];
    #pragma unroll
    for (int mt = 0; mt < 2; ++mt)
        #pragma unroll
        for (int nt = 0; nt < 8; ++nt)
            #pragma unroll
            for (int q = 0; q < 4; ++q) acc[mt][nt][q] = 0.f;

    float aReg[16];

    // --- stage ops ---
    #define CPW(kc, stage) do {                                                   \
        uint32_t _dst = sb + (stage) * STAGEB + 2 * MATB + wStoreOff;             \
        const char* _src = (const char*)(wG + (kc) * BK);                         \
        _Pragma("unroll")                                                         \
        for (int _j = 0; _j < 4; ++_j)                                            \
            asm volatile("cp.async.cg.shared.global [%0], [%1], 16;"              \
                         :: "r"(_dst + _j * 16), "l"(_src + _j * 16) : "memory"); \
        asm volatile("cp.async.commit_group;" ::: "memory");                      \
    } while (0)

    #define LDA(kc) do {                                                          \
        const float4* _p = (const float4*)(aG + (kc) * BK);                       \
        _Pragma("unroll")                                                         \
        for (int _j = 0; _j < 4; ++_j) *(float4*)&aReg[_j * 4] = __ldg(_p + _j);  \
    } while (0)

    #define STA(stage) do {                                                       \
        uint32_t _base = sb + (stage) * STAGEB + aStoreOff;                       \
        _Pragma("unroll")                                                         \
        for (int _h = 0; _h < 2; ++_h) {                                          \
            uint32_t _hi[4], _lo[4];                                              \
            _Pragma("unroll")                                                     \
            for (int _q = 0; _q < 4; ++_q)                                        \
                split2(aReg[_h * 8 + _q * 2], aReg[_h * 8 + _q * 2 + 1],          \
                       _hi[_q], _lo[_q]);                                         \
            asm volatile("st.shared.v4.b32 [%0], {%1,%2,%3,%4};"                  \
                :: "r"(_base + _h * 16),                                          \
                   "r"(_hi[0]), "r"(_hi[1]), "r"(_hi[2]), "r"(_hi[3]) : "memory");\
            asm volatile("st.shared.v4.b32 [%0], {%1,%2,%3,%4};"                  \
                :: "r"(_base + MATB + _h * 16),                                   \
                   "r"(_lo[0]), "r"(_lo[1]), "r"(_lo[2]), "r"(_lo[3]) : "memory");\
        }                                                                         \
    } while (0)

    #define COMPUTE(stage) do {                                                   \
        uint32_t _Ab = sb + (stage) * STAGEB;                                     \
        uint32_t _Bb = _Ab + 2 * MATB;                                            \
        _Pragma("unroll")                                                         \
        for (int _ks = 0; _ks < 2; ++_ks) {                                       \
            uint32_t _ahi[2][4], _alo[2][4], _bf[4][4];                           \
            _Pragma("unroll")                                                     \
            for (int _mt = 0; _mt < 2; ++_mt) {                                   \
                uint32_t _ad = _Ab + aOff + _mt * 16 * RS + _ks * 32;             \
                ldsm4(_ahi[_mt], _ad);                                            \
                ldsm4(_alo[_mt], _ad + MATB);                                     \
            }                                                                     \
            _Pragma("unroll")                                                     \
            for (int _p = 0; _p < 4; ++_p)                                        \
                ldsm4(_bf[_p], _Bb + bOff + _p * 16 * RS + _ks * 32);             \
            _Pragma("unroll")                                                     \
            for (int _mt = 0; _mt < 2; ++_mt)                                     \
                _Pragma("unroll")                                                 \
                for (int _nt = 0; _nt < 8; ++_nt) {                               \
                    uint32_t _b0 = _bf[_nt >> 1][(_nt & 1) * 2];                  \
                    uint32_t _b1 = _bf[_nt >> 1][(_nt & 1) * 2 + 1];              \
                    mma16816(acc[_mt][_nt], _ahi[_mt], _b0, _b1);                 \
                    mma16816(acc[_mt][_nt], _alo[_mt], _b0, _b1);                 \
                }                                                                 \
            _Pragma("unroll")                                                     \
            for (int _p = 0; _p < 4; ++_p)                                        \
                ldsm4(_bf[_p], _Bb + MATB + bOff + _p * 16 * RS + _ks * 32);      \
            _Pragma("unroll")                                                     \
            for (int _mt = 0; _mt < 2; ++_mt)                                     \
                _Pragma("unroll")                                                 \
                for (int _nt = 0; _nt < 8; ++_nt)                                 \
                    mma16816(acc[_mt][_nt], _ahi[_mt],                            \
                             _bf[_nt >> 1][(_nt & 1) * 2],                        \
                             _bf[_nt >> 1][(_nt & 1) * 2 + 1]);                   \
        }                                                                         \
    } while (0)

    // prologue: chunk 0 into stage 0
    CPW(0, 0);
    LDA(0);
    STA(0);
    asm volatile("cp.async.wait_group 0;" ::: "memory");
    __syncthreads();

    for (int kc = 0; kc < NCH; ++kc) {
        const int st = kc & 1;
        if (kc + 1 < NCH) {
            CPW(kc + 1, st ^ 1);
            LDA(kc + 1);
        }
        COMPUTE(st);
        if (kc + 1 < NCH) {
            STA(st ^ 1);
            asm volatile("cp.async.wait_group 0;" ::: "memory");
            __syncthreads();
        }
    }

    // epilogue: fragment rows g=lane>>2, cols (lane&3)*2
    #pragma unroll
    for (int mt = 0; mt < 2; ++mt) {
        int row = m0 + wm + mt * 16 + (lane >> 2);
        #pragma unroll
        for (int nt = 0; nt < 8; ++nt) {
            int col = n0 + wn + nt * 8 + (lane & 3) * 2;
            *(float2*)&C[(size_t)row * NDIM + col] =
                make_float2(acc[mt][nt][0], acc[mt][nt][1]);
            *(float2*)&C[(size_t)(row + 8) * NDIM + col] =
                make_float2(acc[mt][nt][2], acc[mt][nt][3]);
        }
    }
}

// ---------------------------------------------------------------------------
// finalize: diff scalar appended after res
// ---------------------------------------------------------------------------
__global__ void finalize_kernel(float* __restrict__ out, long n_res, long out_size) {
    if (out_size > n_res)
        out[n_res] = (float)(d_diff_acc * (1.0 / (double)(NROWS * DIMQ)));
}

// ---------------------------------------------------------------------------
// launch
// ---------------------------------------------------------------------------
extern "C" void kernel_launch(void* const* d_in, const int* in_sizes, int n_in,
                              void* d_out, int out_size) {
    const float* x      = (const float*)d_in[0];
    const float* weight = (const float*)d_in[1];
    const float* embed  = (const float*)d_in[2];
    float* out = (float*)d_out;

    const int b = in_sizes[0] / KDIM;              // 8192

    init_kernel<<<1, N_EMBED>>>(embed);
    quantize_kernel<<<NROWS / 32, 256>>>(weight, embed);
    split_kernel<<<dim3(16, 16), dim3(32, 8)>>>();

    static int smem_set = 0;
    if (!smem_set) {
        cudaFuncSetAttribute(gemm_mma_kernel,
                             cudaFuncAttributeMaxDynamicSharedMemorySize, SMEMB);
        smem_set = 1;
    }
    dim3 grid(NDIM / 128, b / 128);                // (4, 64)
    gemm_mma_kernel<<<grid, 256, SMEMB>>>(x, out);

    finalize_kernel<<<1, 1>>>(out, (long)b * NDIM, (long)out_size);
}

// round 7
// speedup vs baseline: 3.1275x; 2.4881x over previous
#include <cuda_runtime.h>
#include <cuda_bf16.h>
#include <cstdint>

// Problem constants
#define N_EMBED 512
#define DIMQ    64          // IN_MEM*OUT_MEM
#define NROWS   4096        // IN_G*OUT_G
#define KDIM    512
#define NDIM    512

// Scratch (no cudaMalloc allowed)
__device__ __nv_bfloat16  d_WtHi[NDIM * KDIM];    // W^T hi  [n][k]
__device__ __nv_bfloat16  d_WtLo[NDIM * KDIM];    // W^T lo  [n][k]
__device__ float          d_e2[N_EMBED];
__device__ double         d_diff_acc;

// ---------------------------------------------------------------------------
// helpers
// ---------------------------------------------------------------------------
__device__ __forceinline__ uint32_t smem_u32(const void* p) {
    uint32_t a;
    asm("{ .reg .u64 t; cvta.to.shared.u64 t, %1; cvt.u32.u64 %0, t; }" : "=r"(a) : "l"(p));
    return a;
}
__device__ __forceinline__ void split2(float a, float b, uint32_t& h, uint32_t& l) {
    __nv_bfloat16 ah = __float2bfloat16_rn(a);
    __nv_bfloat16 bh = __float2bfloat16_rn(b);
    __nv_bfloat16 al = __float2bfloat16_rn(a - __bfloat162float(ah));
    __nv_bfloat16 bl = __float2bfloat16_rn(b - __bfloat162float(bh));
    __nv_bfloat162 hv; hv.x = ah; hv.y = bh;
    __nv_bfloat162 lv; lv.x = al; lv.y = bl;
    h = *(uint32_t*)&hv; l = *(uint32_t*)&lv;
}
__device__ __forceinline__ void ldsm4(uint32_t* r, uint32_t addr) {
    asm volatile("ldmatrix.sync.aligned.m8n8.x4.shared.b16 {%0,%1,%2,%3}, [%4];"
                 : "=r"(r[0]), "=r"(r[1]), "=r"(r[2]), "=r"(r[3]) : "r"(addr));
}
__device__ __forceinline__ void mma16816(float* c, const uint32_t* a,
                                         uint32_t b0, uint32_t b1) {
    asm volatile("mma.sync.aligned.m16n8k16.row.col.f32.bf16.bf16.f32 "
                 "{%0,%1,%2,%3}, {%4,%5,%6,%7}, {%8,%9}, {%0,%1,%2,%3};"
                 : "+f"(c[0]), "+f"(c[1]), "+f"(c[2]), "+f"(c[3])
                 : "r"(a[0]), "r"(a[1]), "r"(a[2]), "r"(a[3]), "r"(b0), "r"(b1));
}

// ---------------------------------------------------------------------------
// init: per-code squared norms + zero accumulator
// ---------------------------------------------------------------------------
__global__ void init_kernel(const float* __restrict__ embed) {
    int j = threadIdx.x;
    float s = 0.f;
    #pragma unroll 8
    for (int d = 0; d < DIMQ; ++d) {
        float e = embed[d * N_EMBED + j];
        s += e * e;
    }
    d_e2[j] = s;
    if (j == 0) d_diff_acc = 0.0;
}

// ---------------------------------------------------------------------------
// quantize v2: register-blocked dots (32 rows/block, thread = 4 rows x 16
// codes strided by 128 for coalescing), argmin with first-index tie-break,
// then split hi/lo and write straight into d_WtHi/d_WtLo (GEMM layout).
// grid 128 x 256 threads.
// ---------------------------------------------------------------------------
__global__ __launch_bounds__(256) void quantize_kernel(
    const float* __restrict__ w,        // [4096,64] flat
    const float* __restrict__ embed)    // [64,512]
{
    __shared__ float  ws[32][DIMQ];     // w tile
    __shared__ double blk_diff[8];

    const int tid = threadIdx.x;
    const int ty  = tid >> 5;           // warp id = row group (4 rows)
    const int tx  = tid & 31;           // lane
    const int row0 = blockIdx.x * 32;

    // load w tile: thread -> row tid>>3, cols (tid&7)*8 .. +8
    {
        const int r = tid >> 3;
        const int c = (tid & 7) * 8;
        const float4* src = (const float4*)(w + (size_t)(row0 + r) * DIMQ + c);
        *(float4*)&ws[r][c]     = __ldg(src);
        *(float4*)&ws[r][c + 4] = __ldg(src + 1);
    }
    __syncthreads();

    // dots: acc[r][g*4+j] for code c = g*128 + tx*4 + j
    float acc[4][16];
    #pragma unroll
    for (int r = 0; r < 4; ++r)
        #pragma unroll
        for (int c = 0; c < 16; ++c) acc[r][c] = 0.f;

    #pragma unroll 2
    for (int d = 0; d < DIMQ; ++d) {
        float e[16];
        #pragma unroll
        for (int g = 0; g < 4; ++g)
            *(float4*)&e[g * 4] = __ldg((const float4*)(embed + d * N_EMBED + g * 128 + tx * 4));
        float wv[4];
        #pragma unroll
        for (int r = 0; r < 4; ++r) wv[r] = ws[ty * 4 + r][d];
        #pragma unroll
        for (int r = 0; r < 4; ++r)
            #pragma unroll
            for (int c = 0; c < 16; ++c)
                acc[r][c] += wv[r] * e[c];
    }

    // per-row argmin + quant scatter
    float diff_local = 0.f;
    #pragma unroll
    for (int r = 0; r < 4; ++r) {
        float best = 3.4e38f;
        int   bidx = 0;
        #pragma unroll
        for (int g = 0; g < 4; ++g)
            #pragma unroll
            for (int j = 0; j < 4; ++j) {
                int c = g * 128 + tx * 4 + j;       // ascending within thread
                float s = d_e2[c] - 2.f * acc[r][g * 4 + j];
                if (s < best) { best = s; bidx = c; }
            }
        #pragma unroll
        for (int off = 16; off >= 1; off >>= 1) {
            float ob = __shfl_xor_sync(0xffffffffu, best, off);
            int   oi = __shfl_xor_sync(0xffffffffu, bidx, off);
            if (ob < best || (ob == best && oi < bidx)) { best = ob; bidx = oi; }
        }
        // all lanes agree on bidx for this row
        const int rl  = ty * 4 + r;
        const int row = row0 + rl;
        const int ig = row >> 6;
        const int og = row & 63;
        // lane covers om = tx&7, i pair = (tx>>3)*2
        const int om = tx & 7;
        const int i0 = (tx >> 3) * 2;
        const int d0 = i0 * 8 + om;
        const int d1 = d0 + 8;
        float q0 = __ldg(embed + d0 * N_EMBED + bidx);
        float q1 = __ldg(embed + d1 * N_EMBED + bidx);
        float w0 = ws[rl][d0], w1 = ws[rl][d1];
        float df0 = q0 - w0, df1 = q1 - w1;
        diff_local += df0 * df0 + df1 * df1;
        uint32_t h, l;
        split2(q0, q1, h, l);
        const size_t off_nk = (size_t)(og * 8 + om) * KDIM + ig * 8 + i0;
        *(uint32_t*)&d_WtHi[off_nk] = h;
        *(uint32_t*)&d_WtLo[off_nk] = l;
    }

    // block-reduce diff, one atomic per block
    #pragma unroll
    for (int off = 16; off >= 1; off >>= 1)
        diff_local += __shfl_xor_sync(0xffffffffu, diff_local, off);
    if (tx == 0) blk_diff[ty] = (double)diff_local;
    __syncthreads();
    if (tid == 0) {
        double s = 0.0;
        #pragma unroll
        for (int i = 0; i < 8; ++i) s += blk_diff[i];
        atomicAdd(&d_diff_acc, s);
    }
}

// ---------------------------------------------------------------------------
// HMMA GEMM: C[8192,512] = x @ W via bf16 split (3 products), fp32 accum.
// CTA 128x128, 8 warps (warp tile 32x64), BK=32 fp32 per chunk, 16 chunks,
// double-buffered smem, cp.async for W, mma.sync bf16. 2 CTAs/SM (1 wave).
// ---------------------------------------------------------------------------
#define BK      32
#define NCH     (KDIM / BK)         // 16
#define RS      80                  // smem row stride bytes
#define MATB    (128 * RS)          // 10240 per matrix
#define STAGEB  (4 * MATB)          // 40960 per stage (Ahi, Alo, Whi, Wlo)
#define SMEMB   (2 * STAGEB)        // 81920

__global__ __launch_bounds__(256, 2) void gemm_mma_kernel(
    const float* __restrict__ A,    // x [B,512]
    float* __restrict__ C)          // res [B,512]
{
    extern __shared__ char smem[];
    const uint32_t sb = smem_u32(smem);
    const int tid  = threadIdx.x;
    const int lane = tid & 31;
    const int wid  = tid >> 5;
    const int m0 = blockIdx.y * 128;
    const int n0 = blockIdx.x * 128;
    const int wm = (wid & 3) * 32;      // warp M origin in tile
    const int wn = (wid >> 2) * 64;     // warp N origin in tile

    const uint32_t aOff = (uint32_t)(wm + (lane & 15)) * RS + ((lane >> 4) * 16);
    const uint32_t bOff = (uint32_t)(wn + ((lane >> 4) * 8) + (lane & 7)) * RS
                        + (((lane >> 3) & 1) * 16);

    const int ar = tid >> 1;
    const int ac = (tid & 1) * 16;
    const float* aG = A + (size_t)(m0 + ar) * KDIM + ac;
    const uint32_t aStoreOff = (uint32_t)ar * RS + (uint32_t)ac * 2;

    const int wrow = tid & 127;
    const __nv_bfloat16* wG = ((tid < 128) ? d_WtHi : d_WtLo) + (size_t)(n0 + wrow) * KDIM;
    const uint32_t wStoreOff = ((tid < 128) ? 0u : (uint32_t)MATB) + (uint32_t)wrow * RS;

    float acc[2][8][4];
    #pragma unroll
    for (int mt = 0; mt < 2; ++mt)
        #pragma unroll
        for (int nt = 0; nt < 8; ++nt)
            #pragma unroll
            for (int q = 0; q < 4; ++q) acc[mt][nt][q] = 0.f;

    float aReg[16];

    #define CPW(kc, stage) do {                                                   \
        uint32_t _dst = sb + (stage) * STAGEB + 2 * MATB + wStoreOff;             \
        const char* _src = (const char*)(wG + (kc) * BK);                         \
        _Pragma("unroll")                                                         \
        for (int _j = 0; _j < 4; ++_j)                                            \
            asm volatile("cp.async.cg.shared.global [%0], [%1], 16;"              \
                         :: "r"(_dst + _j * 16), "l"(_src + _j * 16) : "memory"); \
        asm volatile("cp.async.commit_group;" ::: "memory");                      \
    } while (0)

    #define LDA(kc) do {                                                          \
        const float4* _p = (const float4*)(aG + (kc) * BK);                       \
        _Pragma("unroll")                                                         \
        for (int _j = 0; _j < 4; ++_j) *(float4*)&aReg[_j * 4] = __ldg(_p + _j);  \
    } while (0)

    #define STA(stage) do {                                                       \
        uint32_t _base = sb + (stage) * STAGEB + aStoreOff;                       \
        _Pragma("unroll")                                                         \
        for (int _h = 0; _h < 2; ++_h) {                                          \
            uint32_t _hi[4], _lo[4];                                              \
            _Pragma("unroll")                                                     \
            for (int _q = 0; _q < 4; ++_q)                                        \
                split2(aReg[_h * 8 + _q * 2], aReg[_h * 8 + _q * 2 + 1],          \
                       _hi[_q], _lo[_q]);                                         \
            asm volatile("st.shared.v4.b32 [%0], {%1,%2,%3,%4};"                  \
                :: "r"(_base + _h * 16),                                          \
                   "r"(_hi[0]), "r"(_hi[1]), "r"(_hi[2]), "r"(_hi[3]) : "memory");\
            asm volatile("st.shared.v4.b32 [%0], {%1,%2,%3,%4};"                  \
                :: "r"(_base + MATB + _h * 16),                                   \
                   "r"(_lo[0]), "r"(_lo[1]), "r"(_lo[2]), "r"(_lo[3]) : "memory");\
        }                                                                         \
    } while (0)

    #define COMPUTE(stage) do {                                                   \
        uint32_t _Ab = sb + (stage) * STAGEB;                                     \
        uint32_t _Bb = _Ab + 2 * MATB;                                            \
        _Pragma("unroll")                                                         \
        for (int _ks = 0; _ks < 2; ++_ks) {                                       \
            uint32_t _ahi[2][4], _alo[2][4], _bf[4][4];                           \
            _Pragma("unroll")                                                     \
            for (int _mt = 0; _mt < 2; ++_mt) {                                   \
                uint32_t _ad = _Ab + aOff + _mt * 16 * RS + _ks * 32;             \
                ldsm4(_ahi[_mt], _ad);                                            \
                ldsm4(_alo[_mt], _ad + MATB);                                     \
            }                                                                     \
            _Pragma("unroll")                                                     \
            for (int _p = 0; _p < 4; ++_p)                                        \
                ldsm4(_bf[_p], _Bb + bOff + _p * 16 * RS + _ks * 32);             \
            _Pragma("unroll")                                                     \
            for (int _mt = 0; _mt < 2; ++_mt)                                     \
                _Pragma("unroll")                                                 \
                for (int _nt = 0; _nt < 8; ++_nt) {                               \
                    uint32_t _b0 = _bf[_nt >> 1][(_nt & 1) * 2];                  \
                    uint32_t _b1 = _bf[_nt >> 1][(_nt & 1) * 2 + 1];              \
                    mma16816(acc[_mt][_nt], _ahi[_mt], _b0, _b1);                 \
                    mma16816(acc[_mt][_nt], _alo[_mt], _b0, _b1);                 \
                }                                                                 \
            _Pragma("unroll")                                                     \
            for (int _p = 0; _p < 4; ++_p)                                        \
                ldsm4(_bf[_p], _Bb + MATB + bOff + _p * 16 * RS + _ks * 32);      \
            _Pragma("unroll")                                                     \
            for (int _mt = 0; _mt < 2; ++_mt)                                     \
                _Pragma("unroll")                                                 \
                for (int _nt = 0; _nt < 8; ++_nt)                                 \
                    mma16816(acc[_mt][_nt], _ahi[_mt],                            \
                             _bf[_nt >> 1][(_nt & 1) * 2],                        \
                             _bf[_nt >> 1][(_nt & 1) * 2 + 1]);                   \
        }                                                                         \
    } while (0)

    CPW(0, 0);
    LDA(0);
    STA(0);
    asm volatile("cp.async.wait_group 0;" ::: "memory");
    __syncthreads();

    for (int kc = 0; kc < NCH; ++kc) {
        const int st = kc & 1;
        if (kc + 1 < NCH) {
            CPW(kc + 1, st ^ 1);
            LDA(kc + 1);
        }
        COMPUTE(st);
        if (kc + 1 < NCH) {
            STA(st ^ 1);
            asm volatile("cp.async.wait_group 0;" ::: "memory");
            __syncthreads();
        }
    }

    #pragma unroll
    for (int mt = 0; mt < 2; ++mt) {
        int row = m0 + wm + mt * 16 + (lane >> 2);
        #pragma unroll
        for (int nt = 0; nt < 8; ++nt) {
            int col = n0 + wn + nt * 8 + (lane & 3) * 2;
            *(float2*)&C[(size_t)row * NDIM + col] =
                make_float2(acc[mt][nt][0], acc[mt][nt][1]);
            *(float2*)&C[(size_t)(row + 8) * NDIM + col] =
                make_float2(acc[mt][nt][2], acc[mt][nt][3]);
        }
    }
}

// ---------------------------------------------------------------------------
// finalize: diff scalar appended after res
// ---------------------------------------------------------------------------
__global__ void finalize_kernel(float* __restrict__ out, long n_res, long out_size) {
    if (out_size > n_res)
        out[n_res] = (float)(d_diff_acc * (1.0 / (double)(NROWS * DIMQ)));
}

// ---------------------------------------------------------------------------
// launch
// ---------------------------------------------------------------------------
extern "C" void kernel_launch(void* const* d_in, const int* in_sizes, int n_in,
                              void* d_out, int out_size) {
    const float* x      = (const float*)d_in[0];
    const float* weight = (const float*)d_in[1];
    const float* embed  = (const float*)d_in[2];
    float* out = (float*)d_out;

    const int b = in_sizes[0] / KDIM;              // 8192

    init_kernel<<<1, N_EMBED>>>(embed);
    quantize_kernel<<<NROWS / 32, 256>>>(weight, embed);

    static int smem_set = 0;
    if (!smem_set) {
        cudaFuncSetAttribute(gemm_mma_kernel,
                             cudaFuncAttributeMaxDynamicSharedMemorySize, SMEMB);
        smem_set = 1;
    }
    dim3 grid(NDIM / 128, b / 128);                // (4, 64)
    gemm_mma_kernel<<<grid, 256, SMEMB>>>(x, out);

    finalize_kernel<<<1, 1>>>(out, (long)b * NDIM, (long)out_size);
}